// round 6
// baseline (speedup 1.0000x reference)
#include <cuda_runtime.h>
#include <math.h>
#include <stdint.h>

#define SEQ   2048
#define BATCH 2
#define DM    1024
#define NH    16
#define HD    64
#define DFF   4096
#define T_    (SEQ*BATCH)

// ---------------- scratch (no allocations allowed) ----------------
__device__ float g_h  [T_*DM];
__device__ float g_q  [BATCH*NH*SEQ*HD];
__device__ float g_k  [BATCH*NH*SEQ*HD];
__device__ float g_v  [BATCH*NH*SEQ*HD];
__device__ float g_ctx[T_*DM];
__device__ float g_x1 [T_*DM];
__device__ float g_h2 [T_*DM];
__device__ float g_ff [T_*DFF];

// ---------------- helpers ----------------
__device__ __forceinline__ uint32_t f2tf(float f) {
    uint32_t u;
    asm("cvt.rna.tf32.f32 %0, %1;" : "=r"(u) : "f"(f));
    return u;
}

__device__ __forceinline__ void mma_tf32(float c[4], const uint32_t a[4], const uint32_t b[2]) {
    asm volatile(
        "mma.sync.aligned.m16n8k8.row.col.f32.tf32.tf32.f32 "
        "{%0,%1,%2,%3}, {%4,%5,%6,%7}, {%8,%9}, {%0,%1,%2,%3};"
        : "+f"(c[0]), "+f"(c[1]), "+f"(c[2]), "+f"(c[3])
        : "r"(a[0]), "r"(a[1]), "r"(a[2]), "r"(a[3]), "r"(b[0]), "r"(b[1]));
}

// ---------------- RMSNorm ----------------
__global__ void rmsnorm_kernel(const float* __restrict__ x, const float* __restrict__ g,
                               float* __restrict__ o) {
    int row = blockIdx.x;
    const float* xr = x + (size_t)row * DM;
    float s = 0.f;
    for (int i = threadIdx.x; i < DM; i += 256) { float v = xr[i]; s += v * v; }
    __shared__ float red[8];
    for (int off = 16; off; off >>= 1) s += __shfl_xor_sync(0xffffffffu, s, off);
    if ((threadIdx.x & 31) == 0) red[threadIdx.x >> 5] = s;
    __syncthreads();
    if (threadIdx.x < 8) {
        float t = red[threadIdx.x];
        for (int off = 4; off; off >>= 1) t += __shfl_xor_sync(0xffu, t, off);
        if (threadIdx.x == 0) red[0] = t;
    }
    __syncthreads();
    float inv = rsqrtf(red[0] * (1.f / DM) + 1e-6f);
    float* orow = o + (size_t)row * DM;
    for (int i = threadIdx.x; i < DM; i += 256) orow[i] = g[i] * xr[i] * inv;
}

// ---------------- tf32 GEMM: 128x128 CTA tile, 4 warps of 64x64, double-buffered ----------------
#define APITCH 36
#define BPITCH 136
#define GEMM_SMEM_BYTES ((2*128*APITCH + 2*32*BPITCH) * 4)

template<int MODE>
__global__ __launch_bounds__(128) void tgemm(
        const float* __restrict__ A,
        const float* __restrict__ B0, const float* __restrict__ B1, const float* __restrict__ B2,
        const float* __restrict__ Res,
        float* __restrict__ O0, float* __restrict__ O1, float* __restrict__ O2,
        int M, int N, int Kd) {
    extern __shared__ uint32_t dsm[];
    uint32_t* AsBase = dsm;                       // [2][128*APITCH] (row, k)
    uint32_t* BsBase = dsm + 2 * 128 * APITCH;    // [2][32*BPITCH]  (k, col)
    int tid = threadIdx.x;
    int row0 = blockIdx.y << 7, col0 = blockIdx.x << 7;
    int lane = tid & 31, warp = tid >> 5;
    int wm = (warp & 1) << 6;    // 0,64
    int wn = (warp >> 1) << 6;   // 0,64
    int g = lane >> 2, t = lane & 3;

    // A loader: one thread per row, 32 floats each (8 float4)
    int ar = tid;
    const float* Ap = A + (size_t)(row0 + ar) * Kd;

    // B loader: 4 threads per k-row, 32 floats each
    int br = tid >> 2;           // 0..31 (k within tile)
    int bc = (tid & 3) << 5;     // 0,32,64,96
    const float* Bp;
    size_t bstride;
    if (MODE == 3) {
        int c = col0 + bc;                 // head chunk: bc%64 in {0,32}, stays in one head
        int which = c >> 10;
        const float* W = (which == 0) ? B0 : ((which == 1) ? B1 : B2);
        int hh = (c >> 6) & 15;
        int kk = c & 63;
        Bp = W + (size_t)hh * DM * HD + kk;
        bstride = HD;
    } else {
        Bp = B0 + col0 + bc;
        bstride = N;
    }

    float4 pa[8], pb[8];
#pragma unroll
    for (int u = 0; u < 8; u++) pa[u] = *(const float4*)(Ap + u * 4);
#pragma unroll
    for (int u = 0; u < 8; u++) pb[u] = *(const float4*)(Bp + (size_t)br * bstride + u * 4);

    float acc[4][8][4];
#pragma unroll
    for (int i = 0; i < 4; i++)
#pragma unroll
        for (int j = 0; j < 8; j++)
#pragma unroll
            for (int v = 0; v < 4; v++) acc[i][j][v] = 0.f;

    // stage tile 0 into buffer 0
#pragma unroll
    for (int u = 0; u < 8; u++) {
        uint4 v = make_uint4(f2tf(pa[u].x), f2tf(pa[u].y), f2tf(pa[u].z), f2tf(pa[u].w));
        *(uint4*)&AsBase[ar * APITCH + u * 4] = v;
    }
#pragma unroll
    for (int u = 0; u < 8; u++) {
        uint4 v = make_uint4(f2tf(pb[u].x), f2tf(pb[u].y), f2tf(pb[u].z), f2tf(pb[u].w));
        *(uint4*)&BsBase[br * BPITCH + bc + u * 4] = v;
    }
    __syncthreads();

    int ktiles = Kd >> 5;
    for (int kt = 0; kt < ktiles; kt++) {
        const uint32_t* As = AsBase + (kt & 1) * (128 * APITCH);
        const uint32_t* Bs = BsBase + (kt & 1) * (32 * BPITCH);
        bool has_next = (kt + 1 < ktiles);
        if (has_next) {
            int k0 = (kt + 1) << 5;
#pragma unroll
            for (int u = 0; u < 8; u++) pa[u] = *(const float4*)(Ap + k0 + u * 4);
#pragma unroll
            for (int u = 0; u < 8; u++)
                pb[u] = *(const float4*)(Bp + (size_t)(k0 + br) * bstride + u * 4);
        }
#pragma unroll
        for (int ks = 0; ks < 32; ks += 8) {
            uint32_t af[4][4];
#pragma unroll
            for (int mt = 0; mt < 4; mt++) {
                int rb = wm + mt * 16;
                af[mt][0] = As[(rb + g) * APITCH + ks + t];
                af[mt][1] = As[(rb + g + 8) * APITCH + ks + t];
                af[mt][2] = As[(rb + g) * APITCH + ks + t + 4];
                af[mt][3] = As[(rb + g + 8) * APITCH + ks + t + 4];
            }
#pragma unroll
            for (int nt = 0; nt < 8; nt++) {
                uint32_t bf[2];
                int cb = wn + nt * 8 + g;
                bf[0] = Bs[(ks + t) * BPITCH + cb];
                bf[1] = Bs[(ks + t + 4) * BPITCH + cb];
#pragma unroll
                for (int mt = 0; mt < 4; mt++) mma_tf32(acc[mt][nt], af[mt], bf);
            }
        }
        if (has_next) {
            uint32_t* An = AsBase + ((kt + 1) & 1) * (128 * APITCH);
            uint32_t* Bn = BsBase + ((kt + 1) & 1) * (32 * BPITCH);
#pragma unroll
            for (int u = 0; u < 8; u++) {
                uint4 v = make_uint4(f2tf(pa[u].x), f2tf(pa[u].y), f2tf(pa[u].z), f2tf(pa[u].w));
                *(uint4*)&An[ar * APITCH + u * 4] = v;
            }
#pragma unroll
            for (int u = 0; u < 8; u++) {
                uint4 v = make_uint4(f2tf(pb[u].x), f2tf(pb[u].y), f2tf(pb[u].z), f2tf(pb[u].w));
                *(uint4*)&Bn[br * BPITCH + bc + u * 4] = v;
            }
        }
        __syncthreads();
    }

    // epilogue
#pragma unroll
    for (int mt = 0; mt < 4; mt++) {
#pragma unroll
        for (int nt = 0; nt < 8; nt++) {
            int r = row0 + wm + mt * 16 + g;
            int c = col0 + wn + nt * 8 + t * 2;
            float2 v0 = make_float2(acc[mt][nt][0], acc[mt][nt][1]);
            float2 v1 = make_float2(acc[mt][nt][2], acc[mt][nt][3]);
            if (MODE == 3) {
                int which = c >> 10, hh = (c >> 6) & 15, kk = c & 63;
                float* O = (which == 0) ? O0 : ((which == 1) ? O1 : O2);
                int b = r & 1;
                int s0_ = r >> 1;
                int s1_ = (r + 8) >> 1;
                *(float2*)(O + ((size_t)(b * NH + hh) * SEQ + s0_) * HD + kk) = v0;
                *(float2*)(O + ((size_t)(b * NH + hh) * SEQ + s1_) * HD + kk) = v1;
            } else {
                size_t i0 = (size_t)r * N + c;
                size_t i1 = (size_t)(r + 8) * N + c;
                if (MODE == 1) {
                    v0.x = v0.x / (1.f + __expf(-v0.x));
                    v0.y = v0.y / (1.f + __expf(-v0.y));
                    v1.x = v1.x / (1.f + __expf(-v1.x));
                    v1.y = v1.y / (1.f + __expf(-v1.y));
                } else if (MODE == 2) {
                    float2 e0 = *(const float2*)&Res[i0];
                    float2 e1 = *(const float2*)&Res[i1];
                    v0.x += e0.x; v0.y += e0.y;
                    v1.x += e1.x; v1.y += e1.y;
                }
                *(float2*)&O0[i0] = v0;
                *(float2*)&O0[i1] = v1;
            }
        }
    }
}

// ---------------- flash attention on tensor cores (tf32) ----------------
// 64 query rows per block, 8 warps: wm=(warp&3)*16 (M), wn=(warp>>2)*32 (N)
#define QP 68
#define KP 72
#define VP 72
#define SP 68
#define ATTN_SMEM_FLOATS (64*QP + 64*KP + 64*VP + 64*SP + 192)

__global__ __launch_bounds__(256, 2) void attn_kernel(
        const float* __restrict__ Q, const float* __restrict__ K,
        const float* __restrict__ V, float* __restrict__ ctx) {
    extern __shared__ float sm[];
    uint32_t* Qs  = (uint32_t*)sm;           // [64][QP] tf32, A-layout (row, k=hd)
    uint32_t* KsT = Qs + 64 * QP;            // [64][KP] tf32, (k=hd, n=key)
    uint32_t* Vs  = KsT + 64 * KP;           // [64][VP] tf32, (k=key, n=hd)
    float*    Ss  = (float*)(Vs + 64 * VP);  // [64][SP] scores / probs(tf32 bits)
    float* sm_m = Ss + 64 * SP;
    float* sm_l = sm_m + 64;
    float* sm_a = sm_l + 64;

    int s0 = blockIdx.x * 64, hh = blockIdx.y, b = blockIdx.z;
    int tid = threadIdx.x;
    int lane = tid & 31, warp = tid >> 5;
    int wm = (warp & 3) << 4;   // 0,16,32,48
    int wn = (warp >> 2) << 5;  // 0,32
    int g = lane >> 2, t = lane & 3;
    const size_t bh = ((size_t)b * NH + hh) * SEQ * HD;
    const float* Qp = Q + bh;
    const float* Kp = K + bh;
    const float* Vp = V + bh;

    // load Q tile (scaled, tf32)
    {
        int r = tid >> 2, c4 = (tid & 3) << 4;
        const float scale = 0.125f;
#pragma unroll
        for (int u = 0; u < 4; u++) {
            float4 qv = *(const float4*)&Qp[(size_t)(s0 + r) * HD + c4 + u * 4];
            uint4 v = make_uint4(f2tf(qv.x * scale), f2tf(qv.y * scale),
                                 f2tf(qv.z * scale), f2tf(qv.w * scale));
            *(uint4*)&Qs[r * QP + c4 + u * 4] = v;
        }
    }
    if (tid < 64) { sm_m[tid] = -1e30f; sm_l[tid] = 0.f; }

    float oacc[4][4];
#pragma unroll
    for (int nt = 0; nt < 4; nt++)
#pragma unroll
        for (int v = 0; v < 4; v++) oacc[nt][v] = 0.f;

    for (int j0 = 0; j0 <= s0; j0 += 64) {
        __syncthreads();   // protect K/V/Ss reuse (and Q/stat init)
        {
            int r = tid >> 2, c4 = (tid & 3) << 4;
#pragma unroll
            for (int u = 0; u < 4; u++) {
                float4 kv = *(const float4*)&Kp[(size_t)(j0 + r) * HD + c4 + u * 4];
                KsT[(c4 + u * 4 + 0) * KP + r] = f2tf(kv.x);
                KsT[(c4 + u * 4 + 1) * KP + r] = f2tf(kv.y);
                KsT[(c4 + u * 4 + 2) * KP + r] = f2tf(kv.z);
                KsT[(c4 + u * 4 + 3) * KP + r] = f2tf(kv.w);
                float4 vv = *(const float4*)&Vp[(size_t)(j0 + r) * HD + c4 + u * 4];
                uint4 vb = make_uint4(f2tf(vv.x), f2tf(vv.y), f2tf(vv.z), f2tf(vv.w));
                *(uint4*)&Vs[r * VP + c4 + u * 4] = vb;
            }
        }
        __syncthreads();
        // S = Q @ K^T (tensor cores)
        float sacc[4][4];
#pragma unroll
        for (int nt = 0; nt < 4; nt++)
#pragma unroll
            for (int v = 0; v < 4; v++) sacc[nt][v] = 0.f;
#pragma unroll
        for (int ks = 0; ks < 64; ks += 8) {
            uint32_t af[4];
            af[0] = Qs[(wm + g) * QP + ks + t];
            af[1] = Qs[(wm + g + 8) * QP + ks + t];
            af[2] = Qs[(wm + g) * QP + ks + t + 4];
            af[3] = Qs[(wm + g + 8) * QP + ks + t + 4];
#pragma unroll
            for (int nt = 0; nt < 4; nt++) {
                uint32_t bf[2];
                int cb = wn + nt * 8 + g;
                bf[0] = KsT[(ks + t) * KP + cb];
                bf[1] = KsT[(ks + t + 4) * KP + cb];
                mma_tf32(sacc[nt], af, bf);
            }
        }
        // mask (diagonal tile) + store S to smem
        {
            bool diag = (j0 == s0);
            int r0 = wm + g, r1 = wm + g + 8;
#pragma unroll
            for (int nt = 0; nt < 4; nt++) {
                int c0 = wn + nt * 8 + t * 2;
                float2 v0 = make_float2(sacc[nt][0], sacc[nt][1]);
                float2 v1 = make_float2(sacc[nt][2], sacc[nt][3]);
                if (diag) {
                    if (c0 > r0)     v0.x = -1e30f;
                    if (c0 + 1 > r0) v0.y = -1e30f;
                    if (c0 > r1)     v1.x = -1e30f;
                    if (c0 + 1 > r1) v1.y = -1e30f;
                }
                *(float2*)&Ss[r0 * SP + c0] = v0;
                *(float2*)&Ss[r1 * SP + c0] = v1;
            }
        }
        __syncthreads();
        // online softmax (4 threads per row); write p as tf32 bits
        {
            int r = tid >> 2, c0 = (tid & 3) << 4;
            float mx = -1e30f;
#pragma unroll
            for (int c = 0; c < 16; c++) mx = fmaxf(mx, Ss[r * SP + c0 + c]);
            mx = fmaxf(mx, __shfl_xor_sync(0xffffffffu, mx, 1));
            mx = fmaxf(mx, __shfl_xor_sync(0xffffffffu, mx, 2));
            float m_old = sm_m[r];
            float m_new = fmaxf(m_old, mx);
            float sum = 0.f;
#pragma unroll
            for (int c = 0; c < 16; c++) {
                float p = __expf(Ss[r * SP + c0 + c] - m_new);
                Ss[r * SP + c0 + c] = __uint_as_float(f2tf(p));
                sum += p;
            }
            sum += __shfl_xor_sync(0xffffffffu, sum, 1);
            sum += __shfl_xor_sync(0xffffffffu, sum, 2);
            if ((tid & 3) == 0) {
                float alpha = __expf(m_old - m_new);
                sm_a[r] = alpha;
                sm_m[r] = m_new;
                sm_l[r] = sm_l[r] * alpha + sum;
            }
        }
        __syncthreads();
        // rescale O, then O += P @ V (tensor cores)
        {
            float al0 = sm_a[wm + g], al1 = sm_a[wm + g + 8];
#pragma unroll
            for (int nt = 0; nt < 4; nt++) {
                oacc[nt][0] *= al0; oacc[nt][1] *= al0;
                oacc[nt][2] *= al1; oacc[nt][3] *= al1;
            }
        }
#pragma unroll
        for (int ks = 0; ks < 64; ks += 8) {
            uint32_t af[4];
            af[0] = __float_as_uint(Ss[(wm + g) * SP + ks + t]);
            af[1] = __float_as_uint(Ss[(wm + g + 8) * SP + ks + t]);
            af[2] = __float_as_uint(Ss[(wm + g) * SP + ks + t + 4]);
            af[3] = __float_as_uint(Ss[(wm + g + 8) * SP + ks + t + 4]);
#pragma unroll
            for (int nt = 0; nt < 4; nt++) {
                uint32_t bf[2];
                int cb = wn + nt * 8 + g;
                bf[0] = Vs[(ks + t) * VP + cb];
                bf[1] = Vs[(ks + t + 4) * VP + cb];
                mma_tf32(oacc[nt], af, bf);
            }
        }
    }
    // normalize, write ctx (S,B,D) head-concat
    {
        float inv0 = 1.f / sm_l[wm + g];
        float inv1 = 1.f / sm_l[wm + g + 8];
        int r0 = s0 + wm + g, r1 = s0 + wm + g + 8;
#pragma unroll
        for (int nt = 0; nt < 4; nt++) {
            int c0 = hh * HD + wn + nt * 8 + t * 2;
            float2 v0 = make_float2(oacc[nt][0] * inv0, oacc[nt][1] * inv0);
            float2 v1 = make_float2(oacc[nt][2] * inv1, oacc[nt][3] * inv1);
            *(float2*)&ctx[((size_t)r0 * BATCH + b) * DM + c0] = v0;
            *(float2*)&ctx[((size_t)r1 * BATCH + b) * DM + c0] = v1;
        }
    }
}

// ---------------- launch ----------------
extern "C" void kernel_launch(void* const* d_in, const int* in_sizes, int n_in,
                              void* d_out, int out_size) {
    const float* x  = (const float*)d_in[0];
    const float* g1 = (const float*)d_in[1];
    const float* g2 = (const float*)d_in[2];
    const float* Wq = (const float*)d_in[3];
    const float* Wk = (const float*)d_in[4];
    const float* Wv = (const float*)d_in[5];
    const float* Wo = (const float*)d_in[6];
    const float* W1 = (const float*)d_in[7];
    const float* W2 = (const float*)d_in[8];
    float* out = (float*)d_out;

    float *h, *q, *k, *v, *ctx, *x1, *h2, *ff;
    cudaGetSymbolAddress((void**)&h,   g_h);
    cudaGetSymbolAddress((void**)&q,   g_q);
    cudaGetSymbolAddress((void**)&k,   g_k);
    cudaGetSymbolAddress((void**)&v,   g_v);
    cudaGetSymbolAddress((void**)&ctx, g_ctx);
    cudaGetSymbolAddress((void**)&x1,  g_x1);
    cudaGetSymbolAddress((void**)&h2,  g_h2);
    cudaGetSymbolAddress((void**)&ff,  g_ff);

    const int attn_smem = ATTN_SMEM_FLOATS * 4;
    cudaFuncSetAttribute(attn_kernel, cudaFuncAttributeMaxDynamicSharedMemorySize, attn_smem);
    cudaFuncSetAttribute(tgemm<1>, cudaFuncAttributeMaxDynamicSharedMemorySize, GEMM_SMEM_BYTES);
    cudaFuncSetAttribute(tgemm<2>, cudaFuncAttributeMaxDynamicSharedMemorySize, GEMM_SMEM_BYTES);
    cudaFuncSetAttribute(tgemm<3>, cudaFuncAttributeMaxDynamicSharedMemorySize, GEMM_SMEM_BYTES);

    // 1. h = rmsnorm(x, g1)
    rmsnorm_kernel<<<T_, 256>>>(x, g1, h);
    // 2. fused QKV projection
    tgemm<3><<<dim3(3 * DM / 128, T_ / 128), 128, GEMM_SMEM_BYTES>>>(
        h, Wq, Wk, Wv, nullptr, q, k, v, T_, 3 * DM, DM);
    // 3. flash attention -> ctx (S,B,D)
    attn_kernel<<<dim3(SEQ / 64, NH, BATCH), 256, attn_smem>>>(q, k, v, ctx);
    // 4. x1 = x + ctx @ Wo
    tgemm<2><<<dim3(DM / 128, T_ / 128), 128, GEMM_SMEM_BYTES>>>(
        ctx, Wo, nullptr, nullptr, x, x1, nullptr, nullptr, T_, DM, DM);
    // 5. h2 = rmsnorm(x1, g2)
    rmsnorm_kernel<<<T_, 256>>>(x1, g2, h2);
    // 6. ff = silu(h2 @ W1)
    tgemm<1><<<dim3(DFF / 128, T_ / 128), 128, GEMM_SMEM_BYTES>>>(
        h2, W1, nullptr, nullptr, nullptr, ff, nullptr, nullptr, T_, DFF, DM);
    // 7. out = x1 + ff @ W2
    tgemm<2><<<dim3(DM / 128, T_ / 128), 128, GEMM_SMEM_BYTES>>>(
        ff, W2, nullptr, nullptr, x1, out, nullptr, nullptr, T_, DM, DFF);
}

// round 7
// speedup vs baseline: 1.5311x; 1.5311x over previous
#include <cuda_runtime.h>
#include <math.h>
#include <stdint.h>

#define SEQ   2048
#define BATCH 2
#define DM    1024
#define NH    16
#define HD    64
#define DFF   4096
#define T_    (SEQ*BATCH)

// ---------------- scratch (no allocations allowed) ----------------
__device__ float g_h  [T_*DM];
__device__ float g_q  [BATCH*NH*SEQ*HD];
__device__ float g_k  [BATCH*NH*SEQ*HD];
__device__ float g_v  [BATCH*NH*SEQ*HD];
__device__ float g_ctx[T_*DM];
__device__ float g_x1 [T_*DM];
__device__ float g_h2 [T_*DM];
__device__ float g_ff [T_*DFF];

// ---------------- helpers ----------------
__device__ __forceinline__ uint32_t f2tf(float f) {
    uint32_t u;
    asm("cvt.rna.tf32.f32 %0, %1;" : "=r"(u) : "f"(f));
    return u;
}

__device__ __forceinline__ void mma_tf32(float c[4], const uint32_t a[4], const uint32_t b[2]) {
    asm volatile(
        "mma.sync.aligned.m16n8k8.row.col.f32.tf32.tf32.f32 "
        "{%0,%1,%2,%3}, {%4,%5,%6,%7}, {%8,%9}, {%0,%1,%2,%3};"
        : "+f"(c[0]), "+f"(c[1]), "+f"(c[2]), "+f"(c[3])
        : "r"(a[0]), "r"(a[1]), "r"(a[2]), "r"(a[3]), "r"(b[0]), "r"(b[1]));
}

__device__ __forceinline__ void cp16(uint32_t dst, const void* src) {
    asm volatile("cp.async.cg.shared.global [%0], [%1], 16;" :: "r"(dst), "l"(src));
}

// ---------------- RMSNorm ----------------
__global__ void rmsnorm_kernel(const float* __restrict__ x, const float* __restrict__ g,
                               float* __restrict__ o) {
    int row = blockIdx.x;
    const float* xr = x + (size_t)row * DM;
    float s = 0.f;
    for (int i = threadIdx.x; i < DM; i += 256) { float v = xr[i]; s += v * v; }
    __shared__ float red[8];
    for (int off = 16; off; off >>= 1) s += __shfl_xor_sync(0xffffffffu, s, off);
    if ((threadIdx.x & 31) == 0) red[threadIdx.x >> 5] = s;
    __syncthreads();
    if (threadIdx.x < 8) {
        float t = red[threadIdx.x];
        for (int off = 4; off; off >>= 1) t += __shfl_xor_sync(0xffu, t, off);
        if (threadIdx.x == 0) red[0] = t;
    }
    __syncthreads();
    float inv = rsqrtf(red[0] * (1.f / DM) + 1e-6f);
    float* orow = o + (size_t)row * DM;
    for (int i = threadIdx.x; i < DM; i += 256) orow[i] = g[i] * xr[i] * inv;
}

// ---------------- tf32 GEMM: 128x128 tile, 8 warps of 32x64, cp.async double-buffer ----------------
#define APITCH 36
#define BPITCH 136
#define GEMM_SMEM_BYTES ((2*128*APITCH + 2*32*BPITCH) * 4)

template<int MODE>
__global__ __launch_bounds__(256, 2) void tgemm(
        const float* __restrict__ A,
        const float* __restrict__ B0, const float* __restrict__ B1, const float* __restrict__ B2,
        const float* __restrict__ Res,
        float* __restrict__ O0, float* __restrict__ O1, float* __restrict__ O2,
        int M, int N, int Kd) {
    extern __shared__ uint32_t dsm[];
    int tid = threadIdx.x;
    int row0 = blockIdx.y << 7, col0 = blockIdx.x << 7;
    int lane = tid & 31, warp = tid >> 5;
    int wm = (warp & 3) << 5;    // 0,32,64,96
    int wn = (warp >> 2) << 6;   // 0,64
    int g = lane >> 2, t = lane & 3;

    // A loader: 2 threads per row, 16 floats each (4 x 16B)
    int ar = tid >> 1, ac = (tid & 1) << 4;
    const float* Ap = A + (size_t)(row0 + ar) * Kd + ac;

    // B loader: 32 threads per k-row (4 floats each), rows br, br+8, br+16, br+24
    int br = tid >> 5;
    int bc = (tid & 31) << 2;
    const float* Bp;
    size_t bstride;
    if (MODE == 3) {
        int c = col0 + bc;
        int which = c >> 10;
        const float* W = (which == 0) ? B0 : ((which == 1) ? B1 : B2);
        int hh = (c >> 6) & 15;
        int kk = c & 63;
        Bp = W + (size_t)hh * DM * HD + kk;
        bstride = HD;
    } else {
        Bp = B0 + col0 + bc;
        bstride = N;
    }

    uint32_t as0 = (uint32_t)__cvta_generic_to_shared(dsm);
    uint32_t bs0 = as0 + 2 * 128 * APITCH * 4;
    uint32_t adst = as0 + (ar * APITCH + ac) * 4;
    uint32_t bdst = bs0 + (br * BPITCH + bc) * 4;

    float acc[2][8][4];
#pragma unroll
    for (int i = 0; i < 2; i++)
#pragma unroll
        for (int j = 0; j < 8; j++)
#pragma unroll
            for (int v = 0; v < 4; v++) acc[i][j][v] = 0.f;

    // stage tile 0 into buffer 0
#pragma unroll
    for (int u = 0; u < 4; u++) cp16(adst + u * 16, Ap + u * 4);
#pragma unroll
    for (int u = 0; u < 4; u++)
        cp16(bdst + u * 8 * BPITCH * 4, Bp + (size_t)(br + u * 8) * bstride);
    asm volatile("cp.async.commit_group;");

    int ktiles = Kd >> 5;
    for (int kt = 0; kt < ktiles; kt++) {
        int sel = kt & 1;
        if (kt + 1 < ktiles) {
            int k0 = (kt + 1) << 5;
            uint32_t ad = adst + (sel ^ 1) * (128 * APITCH * 4);
            uint32_t bd = bdst + (sel ^ 1) * (32 * BPITCH * 4);
#pragma unroll
            for (int u = 0; u < 4; u++) cp16(ad + u * 16, Ap + k0 + u * 4);
#pragma unroll
            for (int u = 0; u < 4; u++)
                cp16(bd + u * 8 * BPITCH * 4, Bp + (size_t)(k0 + br + u * 8) * bstride);
            asm volatile("cp.async.commit_group;");
            asm volatile("cp.async.wait_group 1;");
        } else {
            asm volatile("cp.async.wait_group 0;");
        }
        __syncthreads();
        const uint32_t* As = dsm + sel * (128 * APITCH);
        const uint32_t* Bs = dsm + 2 * 128 * APITCH + sel * (32 * BPITCH);
#pragma unroll
        for (int ks = 0; ks < 32; ks += 8) {
            uint32_t af[2][4];
#pragma unroll
            for (int mt = 0; mt < 2; mt++) {
                int rb = wm + mt * 16;
                af[mt][0] = As[(rb + g) * APITCH + ks + t];
                af[mt][1] = As[(rb + g + 8) * APITCH + ks + t];
                af[mt][2] = As[(rb + g) * APITCH + ks + t + 4];
                af[mt][3] = As[(rb + g + 8) * APITCH + ks + t + 4];
            }
#pragma unroll
            for (int nt = 0; nt < 8; nt++) {
                uint32_t bf[2];
                int cb = wn + nt * 8 + g;
                bf[0] = Bs[(ks + t) * BPITCH + cb];
                bf[1] = Bs[(ks + t + 4) * BPITCH + cb];
                mma_tf32(acc[0][nt], af[0], bf);
                mma_tf32(acc[1][nt], af[1], bf);
            }
        }
        __syncthreads();  // all warps done reading `sel` before next iter stages into it
    }

    // epilogue
#pragma unroll
    for (int mt = 0; mt < 2; mt++) {
#pragma unroll
        for (int nt = 0; nt < 8; nt++) {
            int r = row0 + wm + mt * 16 + g;
            int c = col0 + wn + nt * 8 + t * 2;
            float2 v0 = make_float2(acc[mt][nt][0], acc[mt][nt][1]);
            float2 v1 = make_float2(acc[mt][nt][2], acc[mt][nt][3]);
            if (MODE == 3) {
                int which = c >> 10, hh = (c >> 6) & 15, kk = c & 63;
                float* O = (which == 0) ? O0 : ((which == 1) ? O1 : O2);
                int b = r & 1;
                int s0_ = r >> 1;
                int s1_ = (r + 8) >> 1;
                *(float2*)(O + ((size_t)(b * NH + hh) * SEQ + s0_) * HD + kk) = v0;
                *(float2*)(O + ((size_t)(b * NH + hh) * SEQ + s1_) * HD + kk) = v1;
            } else {
                size_t i0 = (size_t)r * N + c;
                size_t i1 = (size_t)(r + 8) * N + c;
                if (MODE == 1) {
                    v0.x = v0.x / (1.f + __expf(-v0.x));
                    v0.y = v0.y / (1.f + __expf(-v0.y));
                    v1.x = v1.x / (1.f + __expf(-v1.x));
                    v1.y = v1.y / (1.f + __expf(-v1.y));
                } else if (MODE == 2) {
                    float2 e0 = *(const float2*)&Res[i0];
                    float2 e1 = *(const float2*)&Res[i1];
                    v0.x += e0.x; v0.y += e0.y;
                    v1.x += e1.x; v1.y += e1.y;
                }
                *(float2*)&O0[i0] = v0;
                *(float2*)&O0[i1] = v1;
            }
        }
    }
}

// ---------------- flash attention on tensor cores (tf32) ----------------
#define QP 68
#define KP 72
#define VP 72
#define SP 68
#define ATTN_SMEM_FLOATS (64*QP + 64*KP + 64*VP + 64*SP + 192)

__global__ __launch_bounds__(256, 2) void attn_kernel(
        const float* __restrict__ Q, const float* __restrict__ K,
        const float* __restrict__ V, float* __restrict__ ctx) {
    extern __shared__ float sm[];
    uint32_t* Qs  = (uint32_t*)sm;           // [64][QP] tf32 (row, k=hd)
    uint32_t* KsT = Qs + 64 * QP;            // [64][KP] tf32 (k=hd, n=key)
    uint32_t* Vs  = KsT + 64 * KP;           // [64][VP] tf32 (k=key, n=hd)
    float*    Ss  = (float*)(Vs + 64 * VP);  // [64][SP]
    float* sm_m = Ss + 64 * SP;
    float* sm_l = sm_m + 64;
    float* sm_a = sm_l + 64;

    int s0 = blockIdx.x * 64, hh = blockIdx.y, b = blockIdx.z;
    int tid = threadIdx.x;
    int lane = tid & 31, warp = tid >> 5;
    int wm = (warp & 3) << 4;
    int wn = (warp >> 2) << 5;
    int g = lane >> 2, t = lane & 3;
    const size_t bh = ((size_t)b * NH + hh) * SEQ * HD;
    const float* Qp = Q + bh;
    const float* Kp = K + bh;
    const float* Vp = V + bh;

    {
        int r = tid >> 2, c4 = (tid & 3) << 4;
        const float scale = 0.125f;
#pragma unroll
        for (int u = 0; u < 4; u++) {
            float4 qv = *(const float4*)&Qp[(size_t)(s0 + r) * HD + c4 + u * 4];
            uint4 v = make_uint4(f2tf(qv.x * scale), f2tf(qv.y * scale),
                                 f2tf(qv.z * scale), f2tf(qv.w * scale));
            *(uint4*)&Qs[r * QP + c4 + u * 4] = v;
        }
    }
    if (tid < 64) { sm_m[tid] = -1e30f; sm_l[tid] = 0.f; }

    float oacc[4][4];
#pragma unroll
    for (int nt = 0; nt < 4; nt++)
#pragma unroll
        for (int v = 0; v < 4; v++) oacc[nt][v] = 0.f;

    for (int j0 = 0; j0 <= s0; j0 += 64) {
        __syncthreads();
        {
            int r = tid >> 2, c4 = (tid & 3) << 4;
#pragma unroll
            for (int u = 0; u < 4; u++) {
                float4 kv = *(const float4*)&Kp[(size_t)(j0 + r) * HD + c4 + u * 4];
                KsT[(c4 + u * 4 + 0) * KP + r] = f2tf(kv.x);
                KsT[(c4 + u * 4 + 1) * KP + r] = f2tf(kv.y);
                KsT[(c4 + u * 4 + 2) * KP + r] = f2tf(kv.z);
                KsT[(c4 + u * 4 + 3) * KP + r] = f2tf(kv.w);
                float4 vv = *(const float4*)&Vp[(size_t)(j0 + r) * HD + c4 + u * 4];
                uint4 vb = make_uint4(f2tf(vv.x), f2tf(vv.y), f2tf(vv.z), f2tf(vv.w));
                *(uint4*)&Vs[r * VP + c4 + u * 4] = vb;
            }
        }
        __syncthreads();
        float sacc[4][4];
#pragma unroll
        for (int nt = 0; nt < 4; nt++)
#pragma unroll
            for (int v = 0; v < 4; v++) sacc[nt][v] = 0.f;
#pragma unroll
        for (int ks = 0; ks < 64; ks += 8) {
            uint32_t af[4];
            af[0] = Qs[(wm + g) * QP + ks + t];
            af[1] = Qs[(wm + g + 8) * QP + ks + t];
            af[2] = Qs[(wm + g) * QP + ks + t + 4];
            af[3] = Qs[(wm + g + 8) * QP + ks + t + 4];
#pragma unroll
            for (int nt = 0; nt < 4; nt++) {
                uint32_t bf[2];
                int cb = wn + nt * 8 + g;
                bf[0] = KsT[(ks + t) * KP + cb];
                bf[1] = KsT[(ks + t + 4) * KP + cb];
                mma_tf32(sacc[nt], af, bf);
            }
        }
        {
            bool diag = (j0 == s0);
            int r0 = wm + g, r1 = wm + g + 8;
#pragma unroll
            for (int nt = 0; nt < 4; nt++) {
                int c0 = wn + nt * 8 + t * 2;
                float2 v0 = make_float2(sacc[nt][0], sacc[nt][1]);
                float2 v1 = make_float2(sacc[nt][2], sacc[nt][3]);
                if (diag) {
                    if (c0 > r0)     v0.x = -1e30f;
                    if (c0 + 1 > r0) v0.y = -1e30f;
                    if (c0 > r1)     v1.x = -1e30f;
                    if (c0 + 1 > r1) v1.y = -1e30f;
                }
                *(float2*)&Ss[r0 * SP + c0] = v0;
                *(float2*)&Ss[r1 * SP + c0] = v1;
            }
        }
        __syncthreads();
        {
            int r = tid >> 2, c0 = (tid & 3) << 4;
            float mx = -1e30f;
#pragma unroll
            for (int c = 0; c < 16; c++) mx = fmaxf(mx, Ss[r * SP + c0 + c]);
            mx = fmaxf(mx, __shfl_xor_sync(0xffffffffu, mx, 1));
            mx = fmaxf(mx, __shfl_xor_sync(0xffffffffu, mx, 2));
            float m_old = sm_m[r];
            float m_new = fmaxf(m_old, mx);
            float sum = 0.f;
#pragma unroll
            for (int c = 0; c < 16; c++) {
                float p = __expf(Ss[r * SP + c0 + c] - m_new);
                Ss[r * SP + c0 + c] = __uint_as_float(f2tf(p));
                sum += p;
            }
            sum += __shfl_xor_sync(0xffffffffu, sum, 1);
            sum += __shfl_xor_sync(0xffffffffu, sum, 2);
            if ((tid & 3) == 0) {
                float alpha = __expf(m_old - m_new);
                sm_a[r] = alpha;
                sm_m[r] = m_new;
                sm_l[r] = sm_l[r] * alpha + sum;
            }
        }
        __syncthreads();
        {
            float al0 = sm_a[wm + g], al1 = sm_a[wm + g + 8];
#pragma unroll
            for (int nt = 0; nt < 4; nt++) {
                oacc[nt][0] *= al0; oacc[nt][1] *= al0;
                oacc[nt][2] *= al1; oacc[nt][3] *= al1;
            }
        }
#pragma unroll
        for (int ks = 0; ks < 64; ks += 8) {
            uint32_t af[4];
            af[0] = __float_as_uint(Ss[(wm + g) * SP + ks + t]);
            af[1] = __float_as_uint(Ss[(wm + g + 8) * SP + ks + t]);
            af[2] = __float_as_uint(Ss[(wm + g) * SP + ks + t + 4]);
            af[3] = __float_as_uint(Ss[(wm + g + 8) * SP + ks + t + 4]);
#pragma unroll
            for (int nt = 0; nt < 4; nt++) {
                uint32_t bf[2];
                int cb = wn + nt * 8 + g;
                bf[0] = Vs[(ks + t) * VP + cb];
                bf[1] = Vs[(ks + t + 4) * VP + cb];
                mma_tf32(oacc[nt], af, bf);
            }
        }
    }
    {
        float inv0 = 1.f / sm_l[wm + g];
        float inv1 = 1.f / sm_l[wm + g + 8];
        int r0 = s0 + wm + g, r1 = s0 + wm + g + 8;
#pragma unroll
        for (int nt = 0; nt < 4; nt++) {
            int c0 = hh * HD + wn + nt * 8 + t * 2;
            float2 v0 = make_float2(oacc[nt][0] * inv0, oacc[nt][1] * inv0);
            float2 v1 = make_float2(oacc[nt][2] * inv1, oacc[nt][3] * inv1);
            *(float2*)&ctx[((size_t)r0 * BATCH + b) * DM + c0] = v0;
            *(float2*)&ctx[((size_t)r1 * BATCH + b) * DM + c0] = v1;
        }
    }
}

// ---------------- launch ----------------
extern "C" void kernel_launch(void* const* d_in, const int* in_sizes, int n_in,
                              void* d_out, int out_size) {
    const float* x  = (const float*)d_in[0];
    const float* g1 = (const float*)d_in[1];
    const float* g2 = (const float*)d_in[2];
    const float* Wq = (const float*)d_in[3];
    const float* Wk = (const float*)d_in[4];
    const float* Wv = (const float*)d_in[5];
    const float* Wo = (const float*)d_in[6];
    const float* W1 = (const float*)d_in[7];
    const float* W2 = (const float*)d_in[8];
    float* out = (float*)d_out;

    float *h, *q, *k, *v, *ctx, *x1, *h2, *ff;
    cudaGetSymbolAddress((void**)&h,   g_h);
    cudaGetSymbolAddress((void**)&q,   g_q);
    cudaGetSymbolAddress((void**)&k,   g_k);
    cudaGetSymbolAddress((void**)&v,   g_v);
    cudaGetSymbolAddress((void**)&ctx, g_ctx);
    cudaGetSymbolAddress((void**)&x1,  g_x1);
    cudaGetSymbolAddress((void**)&h2,  g_h2);
    cudaGetSymbolAddress((void**)&ff,  g_ff);

    const int attn_smem = ATTN_SMEM_FLOATS * 4;
    cudaFuncSetAttribute(attn_kernel, cudaFuncAttributeMaxDynamicSharedMemorySize, attn_smem);
    cudaFuncSetAttribute(tgemm<1>, cudaFuncAttributeMaxDynamicSharedMemorySize, GEMM_SMEM_BYTES);
    cudaFuncSetAttribute(tgemm<2>, cudaFuncAttributeMaxDynamicSharedMemorySize, GEMM_SMEM_BYTES);
    cudaFuncSetAttribute(tgemm<3>, cudaFuncAttributeMaxDynamicSharedMemorySize, GEMM_SMEM_BYTES);

    // 1. h = rmsnorm(x, g1)
    rmsnorm_kernel<<<T_, 256>>>(x, g1, h);
    // 2. fused QKV projection
    tgemm<3><<<dim3(3 * DM / 128, T_ / 128), 256, GEMM_SMEM_BYTES>>>(
        h, Wq, Wk, Wv, nullptr, q, k, v, T_, 3 * DM, DM);
    // 3. flash attention -> ctx (S,B,D)
    attn_kernel<<<dim3(SEQ / 64, NH, BATCH), 256, attn_smem>>>(q, k, v, ctx);
    // 4. x1 = x + ctx @ Wo
    tgemm<2><<<dim3(DM / 128, T_ / 128), 256, GEMM_SMEM_BYTES>>>(
        ctx, Wo, nullptr, nullptr, x, x1, nullptr, nullptr, T_, DM, DM);
    // 5. h2 = rmsnorm(x1, g2)
    rmsnorm_kernel<<<T_, 256>>>(x1, g2, h2);
    // 6. ff = silu(h2 @ W1)
    tgemm<1><<<dim3(DFF / 128, T_ / 128), 256, GEMM_SMEM_BYTES>>>(
        h2, W1, nullptr, nullptr, nullptr, ff, nullptr, nullptr, T_, DFF, DM);
    // 7. out = x1 + ff @ W2
    tgemm<2><<<dim3(DM / 128, T_ / 128), 256, GEMM_SMEM_BYTES>>>(
        ff, W2, nullptr, nullptr, x1, out, nullptr, nullptr, T_, DM, DFF);
}